// round 1
// baseline (speedup 1.0000x reference)
#include <cuda_runtime.h>
#include <math.h>

// ---------------- problem constants ----------------
#define B_   64
#define S_   100
#define D_   768
#define H_   8
#define HD_  96
#define P_   8
#define FF_  3072
#define M_   (B_ * S_)            // 6400 rows
#define NLAYERS 4
#define EPS_ 1e-5f
#define INV_SQRT_HD 0.10206207261596575f   // 1/sqrt(96)

// ---------------- device scratch (no allocation allowed) ----------------
__device__ float g_x[M_ * D_];        // activations
__device__ float g_pooled[M_ * D_];   // mean over params
__device__ float g_enc[M_ * D_];      // param encoder out
__device__ float g_pbias[B_ * H_ * S_ * S_];  // attention bias, layer-invariant
__device__ float g_tmp[M_ * D_];      // attn-out / ffn2-out
__device__ float g_ff[M_ * FF_];      // ffn hidden

// ---------------- elementwise: x = template + positional encoding ----------------
__global__ void add_pe_kernel(const float* __restrict__ t, float* __restrict__ x) {
    int idx = blockIdx.x * 256 + threadIdx.x;
    if (idx >= M_ * D_) return;
    int d = idx % D_;
    int s = (idx / D_) % S_;
    int i2 = d & ~1;  // 2*i
    float div = expf((float)i2 * (-9.210340371976184f / (float)D_)); // -ln(10000)/D
    float ang = (float)s * div;
    float pe = (d & 1) ? cosf(ang) : sinf(ang);
    x[idx] = t[idx] + pe;
}

// ---------------- pooled = mean over P of param_seq ----------------
__global__ void pool_kernel(const float* __restrict__ ps, float* __restrict__ out) {
    int idx = blockIdx.x * 256 + threadIdx.x;
    if (idx >= M_ * D_) return;
    int bs = idx / D_;
    int c  = idx % D_;
    const float* base = ps + (long long)bs * (P_ * D_) + c;
    float s = 0.f;
    #pragma unroll
    for (int p = 0; p < P_; p++) s += base[p * D_];
    out[idx] = s * (1.0f / P_);
}

// ---------------- SGEMM 128x128x8, 256 threads, 8x8 register tile ----------------
// C[M,N] = A[M,K] @ B[K,N] + bias[N], optional exact GELU. All dims % tile == 0.
__device__ __forceinline__ float gelu_exact(float v) {
    return 0.5f * v * (1.0f + erff(v * 0.70710678118654752f));
}

template <int EPI>   // 0: bias only, 1: bias + gelu
__global__ __launch_bounds__(256, 2)
void sgemm_kernel(const float* __restrict__ A, const float* __restrict__ Bm,
                  const float* __restrict__ bias, float* __restrict__ C,
                  int M, int N, int K) {
    __shared__ float As[8][128];
    __shared__ float Bs[8][128];

    const int bx = blockIdx.x;     // N block
    const int by = blockIdx.y;     // M block
    const int tid = threadIdx.x;

    const int a_row = tid >> 1;            // 0..127
    const int a_col = (tid & 1) * 4;       // 0 or 4
    const int b_row = tid >> 5;            // 0..7
    const int b_col = (tid & 31) * 4;      // 0..124

    const int ty = tid >> 4, tx = tid & 15;
    const int row0 = ty * 8, col0 = tx * 8;

    const float* Aptr = A + (long long)(by * 128) * K;
    const float* Bptr = Bm + bx * 128;

    float acc[8][8];
    #pragma unroll
    for (int i = 0; i < 8; i++)
        #pragma unroll
        for (int j = 0; j < 8; j++) acc[i][j] = 0.f;

    for (int k0 = 0; k0 < K; k0 += 8) {
        float4 av = *(const float4*)(Aptr + (long long)a_row * K + k0 + a_col);
        As[a_col + 0][a_row] = av.x;
        As[a_col + 1][a_row] = av.y;
        As[a_col + 2][a_row] = av.z;
        As[a_col + 3][a_row] = av.w;
        *(float4*)(&Bs[b_row][b_col]) = *(const float4*)(Bptr + (long long)(k0 + b_row) * N + b_col);
        __syncthreads();

        #pragma unroll
        for (int k = 0; k < 8; k++) {
            float a_frag[8], b_frag[8];
            #pragma unroll
            for (int i = 0; i < 8; i++) a_frag[i] = As[k][row0 + i];
            #pragma unroll
            for (int j = 0; j < 8; j++) b_frag[j] = Bs[k][col0 + j];
            #pragma unroll
            for (int i = 0; i < 8; i++)
                #pragma unroll
                for (int j = 0; j < 8; j++) acc[i][j] += a_frag[i] * b_frag[j];
        }
        __syncthreads();
    }

    const int gcol = bx * 128 + col0;
    #pragma unroll
    for (int i = 0; i < 8; i++) {
        float* Crow = C + (long long)(by * 128 + row0 + i) * N + gcol;
        #pragma unroll
        for (int j = 0; j < 8; j += 4) {
            float4 v;
            v.x = acc[i][j + 0] + bias[gcol + j + 0];
            v.y = acc[i][j + 1] + bias[gcol + j + 1];
            v.z = acc[i][j + 2] + bias[gcol + j + 2];
            v.w = acc[i][j + 3] + bias[gcol + j + 3];
            if (EPI == 1) {
                v.x = gelu_exact(v.x); v.y = gelu_exact(v.y);
                v.z = gelu_exact(v.z); v.w = gelu_exact(v.w);
            }
            *(float4*)(Crow + j) = v;
        }
    }
}

// ---------------- block-reduce helpers ----------------
__device__ __forceinline__ float warp_sum(float v) {
    #pragma unroll
    for (int o = 16; o; o >>= 1) v += __shfl_down_sync(0xffffffffu, v, o);
    return v;
}

// ---------------- LayerNorm: out = LN(x (+ res)) * g + b  (row length 768) ----------------
__global__ void ln_kernel(const float* __restrict__ x, const float* __restrict__ res,
                          const float* __restrict__ g, const float* __restrict__ b,
                          float* __restrict__ out) {
    const int row = blockIdx.x;
    const int tid = threadIdx.x;  // 256
    const float* xr = x + (long long)row * D_;
    const float* rr = res ? res + (long long)row * D_ : nullptr;

    float v[3];
    float s = 0.f, s2 = 0.f;
    #pragma unroll
    for (int i = 0; i < 3; i++) {
        float t = xr[tid + i * 256];
        if (rr) t += rr[tid + i * 256];
        v[i] = t; s += t; s2 += t * t;
    }

    __shared__ float red[2][8];
    __shared__ float stat[2];
    int lane = tid & 31, wid = tid >> 5;
    s = warp_sum(s); s2 = warp_sum(s2);
    if (lane == 0) { red[0][wid] = s; red[1][wid] = s2; }
    __syncthreads();
    if (wid == 0) {
        float a = (lane < 8) ? red[0][lane] : 0.f;
        float c = (lane < 8) ? red[1][lane] : 0.f;
        a = warp_sum(a); c = warp_sum(c);
        if (lane == 0) {
            float mean = a * (1.0f / D_);
            float var = c * (1.0f / D_) - mean * mean;
            stat[0] = mean;
            stat[1] = rsqrtf(var + EPS_);
        }
    }
    __syncthreads();
    float mean = stat[0], inv = stat[1];
    float* orow = out + (long long)row * D_;
    #pragma unroll
    for (int i = 0; i < 3; i++) {
        int c = tid + i * 256;
        orow[c] = (v[i] - mean) * inv * g[c] + b[c];
    }
}

// ---------------- param_bias[b,h] = (pe_bh @ pe_bh^T) * inv_sqrt_hd ----------------
// One block per (b,h). pe tile 100x96 in smem (zero-padded to 112 rows, stride 97).
__global__ __launch_bounds__(256)
void pbias_kernel(const float* __restrict__ enc, float* __restrict__ pbias) {
    __shared__ float Es[112 * 97];
    const int b = blockIdx.x >> 3;
    const int h = blockIdx.x & 7;
    const int tid = threadIdx.x;
    const float* src = enc + (long long)(b * S_) * D_ + h * HD_;

    for (int i = tid; i < 112 * 96; i += 256) {
        int s = i / 96, d = i - s * 96;
        Es[s * 97 + d] = (s < S_) ? src[(long long)s * D_ + d] : 0.f;
    }
    __syncthreads();

    const int tx = tid & 15, ty = tid >> 4;
    float acc[7][7];
    #pragma unroll
    for (int ii = 0; ii < 7; ii++)
        #pragma unroll
        for (int jj = 0; jj < 7; jj++) acc[ii][jj] = 0.f;

    for (int d = 0; d < 96; d++) {
        float a[7], bb[7];
        #pragma unroll
        for (int ii = 0; ii < 7; ii++) a[ii]  = Es[(ty + 16 * ii) * 97 + d];
        #pragma unroll
        for (int jj = 0; jj < 7; jj++) bb[jj] = Es[(tx + 16 * jj) * 97 + d];
        #pragma unroll
        for (int ii = 0; ii < 7; ii++)
            #pragma unroll
            for (int jj = 0; jj < 7; jj++) acc[ii][jj] += a[ii] * bb[jj];
    }

    float* dst = pbias + (long long)blockIdx.x * (S_ * S_);
    #pragma unroll
    for (int ii = 0; ii < 7; ii++) {
        int i = ty + 16 * ii;
        if (i >= S_) continue;
        #pragma unroll
        for (int jj = 0; jj < 7; jj++) {
            int j = tx + 16 * jj;
            if (j < S_) dst[i * S_ + j] = acc[ii][jj] * INV_SQRT_HD;
        }
    }
}

// ---------------- fused attention per (b,h): scores+bias -> softmax -> @q ----------------
// dynamic smem: Qs[112*97] + Ss[112*101]
#define ATTN_SMEM ((112 * 97 + 112 * 101) * 4)
__global__ __launch_bounds__(256)
void attn_kernel(const float* __restrict__ x, const float* __restrict__ pbias,
                 float* __restrict__ out) {
    extern __shared__ float smem[];
    float* Qs = smem;               // [112][97]
    float* Ss = smem + 112 * 97;    // [112][101]

    const int b = blockIdx.x >> 3;
    const int h = blockIdx.x & 7;
    const int tid = threadIdx.x;
    const float* xb = x + (long long)(b * S_) * D_ + h * HD_;

    for (int i = tid; i < 112 * 96; i += 256) {
        int s = i / 96, d = i - s * 96;
        Qs[s * 97 + d] = (s < S_) ? xb[(long long)s * D_ + d] : 0.f;
    }
    __syncthreads();

    const int tx = tid & 15, ty = tid >> 4;
    // ---- scores = q q^T * scale + bias ----
    {
        float acc[7][7];
        #pragma unroll
        for (int ii = 0; ii < 7; ii++)
            #pragma unroll
            for (int jj = 0; jj < 7; jj++) acc[ii][jj] = 0.f;

        for (int d = 0; d < 96; d++) {
            float a[7], bb[7];
            #pragma unroll
            for (int ii = 0; ii < 7; ii++) a[ii]  = Qs[(ty + 16 * ii) * 97 + d];
            #pragma unroll
            for (int jj = 0; jj < 7; jj++) bb[jj] = Qs[(tx + 16 * jj) * 97 + d];
            #pragma unroll
            for (int ii = 0; ii < 7; ii++)
                #pragma unroll
                for (int jj = 0; jj < 7; jj++) acc[ii][jj] += a[ii] * bb[jj];
        }
        const float* pb = pbias + (long long)blockIdx.x * (S_ * S_);
        #pragma unroll
        for (int ii = 0; ii < 7; ii++) {
            int i = ty + 16 * ii;
            if (i >= S_) continue;
            #pragma unroll
            for (int jj = 0; jj < 7; jj++) {
                int j = tx + 16 * jj;
                if (j < S_)
                    Ss[i * 101 + j] = acc[ii][jj] * INV_SQRT_HD + pb[i * S_ + j];
            }
        }
    }
    __syncthreads();

    // ---- softmax per row (threads 0..99) ----
    if (tid < S_) {
        float* row = Ss + tid * 101;
        float m = -1e30f;
        for (int j = 0; j < S_; j++) m = fmaxf(m, row[j]);
        float sum = 0.f;
        for (int j = 0; j < S_; j++) { float e = expf(row[j] - m); row[j] = e; sum += e; }
        float inv = 1.0f / sum;
        for (int j = 0; j < S_; j++) row[j] *= inv;
    }
    __syncthreads();

    // ---- out = attn @ q  (100 x 96) ----
    {
        float acc[7][6];
        #pragma unroll
        for (int ii = 0; ii < 7; ii++)
            #pragma unroll
            for (int jj = 0; jj < 6; jj++) acc[ii][jj] = 0.f;

        for (int j = 0; j < S_; j++) {
            float a[7], bb[6];
            #pragma unroll
            for (int ii = 0; ii < 7; ii++) a[ii]  = Ss[(ty + 16 * ii) * 101 + j];
            #pragma unroll
            for (int jj = 0; jj < 6; jj++) bb[jj] = Qs[j * 97 + tx + 16 * jj];
            #pragma unroll
            for (int ii = 0; ii < 7; ii++)
                #pragma unroll
                for (int jj = 0; jj < 6; jj++) acc[ii][jj] += a[ii] * bb[jj];
        }
        float* dst = out + (long long)(b * S_) * D_ + h * HD_;
        #pragma unroll
        for (int ii = 0; ii < 7; ii++) {
            int i = ty + 16 * ii;
            if (i >= S_) continue;
            #pragma unroll
            for (int jj = 0; jj < 6; jj++) {
                int dd = tx + 16 * jj;   // < 96 always
                dst[(long long)i * D_ + dd] = acc[ii][jj];
            }
        }
    }
}

// ---------------- final classifier: out[b,:2] = x[b,:] @ Wfc + bfc ----------------
__global__ void fc_kernel(const float* __restrict__ x, const float* __restrict__ Wfc,
                          const float* __restrict__ bfc, float* __restrict__ out) {
    const int b = blockIdx.x;
    const int tid = threadIdx.x;
    const float* xr = x + (long long)b * (S_ * D_);
    float a0 = 0.f, a1 = 0.f;
    for (int i = tid; i < S_ * D_; i += 256) {
        float v = xr[i];
        a0 += v * Wfc[2 * i];
        a1 += v * Wfc[2 * i + 1];
    }
    __shared__ float red[2][8];
    int lane = tid & 31, wid = tid >> 5;
    a0 = warp_sum(a0); a1 = warp_sum(a1);
    if (lane == 0) { red[0][wid] = a0; red[1][wid] = a1; }
    __syncthreads();
    if (wid == 0) {
        float r0 = (lane < 8) ? red[0][lane] : 0.f;
        float r1 = (lane < 8) ? red[1][lane] : 0.f;
        r0 = warp_sum(r0); r1 = warp_sum(r1);
        if (lane == 0) {
            out[2 * b + 0] = r0 + bfc[0];
            out[2 * b + 1] = r1 + bfc[1];
        }
    }
}

// ---------------- launch ----------------
extern "C" void kernel_launch(void* const* d_in, const int* in_sizes, int n_in,
                              void* d_out, int out_size) {
    const float* tseq = (const float*)d_in[0];
    const float* pseq = (const float*)d_in[1];
    const float* Wc  = (const float*)d_in[2];
    const float* bc  = (const float*)d_in[3];
    const float* gp  = (const float*)d_in[4];
    const float* bp  = (const float*)d_in[5];
    const float* W1  = (const float*)d_in[6];
    const float* b1  = (const float*)d_in[7];
    const float* W2  = (const float*)d_in[8];
    const float* b2  = (const float*)d_in[9];
    const float* g1  = (const float*)d_in[10];
    const float* bn1 = (const float*)d_in[11];
    const float* g2  = (const float*)d_in[12];
    const float* bn2 = (const float*)d_in[13];
    const float* Wfc = (const float*)d_in[14];
    const float* bfc = (const float*)d_in[15];
    float* out = (float*)d_out;

    float *x, *pooled, *enc, *pbias, *tmp, *ff;
    cudaGetSymbolAddress((void**)&x, g_x);
    cudaGetSymbolAddress((void**)&pooled, g_pooled);
    cudaGetSymbolAddress((void**)&enc, g_enc);
    cudaGetSymbolAddress((void**)&pbias, g_pbias);
    cudaGetSymbolAddress((void**)&tmp, g_tmp);
    cudaGetSymbolAddress((void**)&ff, g_ff);

    cudaFuncSetAttribute(attn_kernel, cudaFuncAttributeMaxDynamicSharedMemorySize, ATTN_SMEM);

    const int total = M_ * D_;
    add_pe_kernel<<<(total + 255) / 256, 256>>>(tseq, x);
    pool_kernel<<<(total + 255) / 256, 256>>>(pseq, pooled);

    // param encoder: enc = LN(pooled @ Wc + bc)
    sgemm_kernel<0><<<dim3(D_ / 128, M_ / 128), 256>>>(pooled, Wc, bc, enc, M_, D_, D_);
    ln_kernel<<<M_, 256>>>(enc, nullptr, gp, bp, enc);

    // layer-invariant attention bias
    pbias_kernel<<<B_ * H_, 256>>>(enc, pbias);

    for (int l = 0; l < NLAYERS; l++) {
        attn_kernel<<<B_ * H_, 256, ATTN_SMEM>>>(x, pbias, tmp);
        ln_kernel<<<M_, 256>>>(x, tmp, g1, bn1, x);
        sgemm_kernel<1><<<dim3(FF_ / 128, M_ / 128), 256>>>(x, W1, b1, ff, M_, FF_, D_);
        sgemm_kernel<0><<<dim3(D_ / 128, M_ / 128), 256>>>(ff, W2, b2, tmp, M_, D_, FF_);
        ln_kernel<<<M_, 256>>>(x, tmp, g2, bn2, x);
    }

    fc_kernel<<<B_, 256>>>(x, Wfc, bfc, out);
}

// round 3
// speedup vs baseline: 2.0721x; 2.0721x over previous
#include <cuda_runtime.h>
#include <cuda_bf16.h>
#include <math.h>
#include <stdint.h>

// ---------------- problem constants ----------------
#define B_   64
#define S_   100
#define D_   768
#define H_   8
#define HD_  96
#define P_   8
#define FF_  3072
#define M_   (B_ * S_)            // 6400 rows
#define NLAYERS 4
#define EPS_ 1e-5f
#define INV_SQRT_HD 0.10206207261596575f   // 1/sqrt(96)

// ---------------- device scratch ----------------
__device__ float g_x[M_ * D_];
__device__ float g_enc[M_ * D_];
__device__ float g_pbias[B_ * H_ * S_ * S_];
__device__ float g_tmp[M_ * D_];

__device__ __nv_bfloat16 g_xhi[M_ * D_];
__device__ __nv_bfloat16 g_xlo[M_ * D_];
__device__ __nv_bfloat16 g_phi[M_ * D_];
__device__ __nv_bfloat16 g_plo[M_ * D_];
__device__ __nv_bfloat16 g_ffhi[(size_t)M_ * FF_];
__device__ __nv_bfloat16 g_fflo[(size_t)M_ * FF_];
__device__ __nv_bfloat16 g_w1h[(size_t)FF_ * D_];   // [N=3072][K=768]
__device__ __nv_bfloat16 g_w1l[(size_t)FF_ * D_];
__device__ __nv_bfloat16 g_w2h[(size_t)D_ * FF_];   // [N=768][K=3072]
__device__ __nv_bfloat16 g_w2l[(size_t)D_ * FF_];
__device__ __nv_bfloat16 g_wch[(size_t)D_ * D_];    // [N=768][K=768]
__device__ __nv_bfloat16 g_wcl[(size_t)D_ * D_];

// ============================================================
// PTX helpers (mma.sync / ldmatrix / cp.async — all baseline sm_80+)
// ============================================================
__device__ __forceinline__ uint32_t smem_u32(const void* p) {
    uint32_t a;
    asm("{ .reg .u64 t; cvta.to.shared.u64 t, %1; cvt.u32.u64 %0, t; }" : "=r"(a) : "l"(p));
    return a;
}

#define CP_ASYNC16(dst, src) \
    asm volatile("cp.async.cg.shared.global [%0], [%1], 16;\n" :: "r"(dst), "l"(src) : "memory")
#define CP_COMMIT() asm volatile("cp.async.commit_group;\n" ::: "memory")
#define CP_WAIT0()  asm volatile("cp.async.wait_group 0;\n" ::: "memory")
#define CP_WAIT1()  asm volatile("cp.async.wait_group 1;\n" ::: "memory")

#define LDSM4(r, addr) \
    asm volatile("ldmatrix.sync.aligned.m8n8.x4.shared.b16 {%0,%1,%2,%3}, [%4];" \
        : "=r"((r)[0]), "=r"((r)[1]), "=r"((r)[2]), "=r"((r)[3]) : "r"(addr))

#define MMA_BF16(c, a, b) \
    asm volatile("mma.sync.aligned.m16n8k16.row.col.f32.bf16.bf16.f32 " \
        "{%0,%1,%2,%3}, {%4,%5,%6,%7}, {%8,%9}, {%0,%1,%2,%3};" \
        : "+f"((c)[0]), "+f"((c)[1]), "+f"((c)[2]), "+f"((c)[3]) \
        : "r"((a)[0]), "r"((a)[1]), "r"((a)[2]), "r"((a)[3]), "r"((b)[0]), "r"((b)[1]))

__device__ __forceinline__ float gelu_exact(float v) {
    return 0.5f * v * (1.0f + erff(v * 0.70710678118654752f));
}
__device__ __forceinline__ void split_bf16(float v, __nv_bfloat16& h, __nv_bfloat16& l) {
    h = __float2bfloat16(v);
    l = __float2bfloat16(v - __bfloat162float(h));
}

// ============================================================
// GEMM: C[M,N] = A[M,K] @ B^T[N,K] + bias, fp32 via bf16 hi/lo x3 on HMMA
// EPI 0: fp32 out.  EPI 1: gelu then bf16 hi/lo out.
// M%128==0, N%128==0, K%32==0.
// smem tile per stage: Ah[128][40], Al, Bh[128][40], Bl  (bf16, 80B rows)
// ============================================================
#define BMT 128
#define BNT 128
#define BKS 32
#define NSTAGE 3
#define MATB 10240u                // 128*40*2 bytes
#define BUFB (4 * MATB)            // 40960
#define GEMM_SMEM (NSTAGE * BUFB)  // 122880

template <int EPI>
__global__ __launch_bounds__(256)
void mma_gemm(const __nv_bfloat16* __restrict__ Ah_, const __nv_bfloat16* __restrict__ Al_,
              const __nv_bfloat16* __restrict__ Bh_, const __nv_bfloat16* __restrict__ Bl_,
              const float* __restrict__ bias,
              float* __restrict__ Cf, __nv_bfloat16* __restrict__ Ch,
              __nv_bfloat16* __restrict__ Cl,
              int M, int N, int K)
{
    extern __shared__ char dsm[];
    const uint32_t sb0 = smem_u32(dsm);
    const int tid = threadIdx.x;
    const int wid = tid >> 5, lane = tid & 31;
    const int wm = wid >> 2, wn = wid & 3;          // warp tile: 64 x 32
    const int row0 = blockIdx.y * BMT, col0 = blockIdx.x * BNT;
    const int NS = K / BKS;

    float acc[4][4][4];
    #pragma unroll
    for (int i = 0; i < 4; i++)
        #pragma unroll
        for (int j = 0; j < 4; j++)
            #pragma unroll
            for (int k = 0; k < 4; k++) acc[i][j][k] = 0.f;

    // ldmatrix per-lane base offsets (bytes, within one stage buffer)
    // A m16k16 frag: lanes 0-15 rows, lanes 16-31 same rows at k+8
    const uint32_t aoff = (uint32_t)((wm * 64 + (lane & 15)) * 80 + (lane >> 4) * 16);
    // B pair of n8k16 frags: groups of 8 lanes -> (n-half, k-half)
    const uint32_t boff = (uint32_t)((wn * 32 + ((lane >> 4) << 3) + (lane & 7)) * 80
                                     + ((lane >> 3) & 1) * 16);

    auto load_step = [&](int s) {
        const uint32_t sb = sb0 + (uint32_t)(s % NSTAGE) * BUFB;
        const int k0 = s * BKS;
        #pragma unroll
        for (int i = 0; i < 8; i++) {
            int u = i * 256 + tid;
            int mat = u >> 9;          // 0 Ah, 1 Al, 2 Bh, 3 Bl
            int v = u & 511;
            int r = v >> 2, c = v & 3;
            const __nv_bfloat16* src;
            if (mat == 0)      src = Ah_ + (size_t)(row0 + r) * K + k0 + c * 8;
            else if (mat == 1) src = Al_ + (size_t)(row0 + r) * K + k0 + c * 8;
            else if (mat == 2) src = Bh_ + (size_t)(col0 + r) * K + k0 + c * 8;
            else               src = Bl_ + (size_t)(col0 + r) * K + k0 + c * 8;
            CP_ASYNC16(sb + (uint32_t)mat * MATB + (uint32_t)(r * 80 + c * 16), src);
        }
        CP_COMMIT();
    };

    load_step(0);
    load_step(1);

    for (int s = 0; s < NS; s++) {
        if (s < NS - 1) { CP_WAIT1(); } else { CP_WAIT0(); }
        __syncthreads();
        if (s + 2 < NS) load_step(s + 2);   // writes stage (s+2)%3 == (s-1)%3: free after the barrier

        const uint32_t sb = sb0 + (uint32_t)(s % NSTAGE) * BUFB;
        #pragma unroll
        for (int kh = 0; kh < 2; kh++) {     // two k16 halves of the k32 step
            uint32_t ah[4][4], al[4][4], bh[4][2], bl[4][2];
            #pragma unroll
            for (int mf = 0; mf < 4; mf++) {
                LDSM4(ah[mf], sb + aoff + (uint32_t)(mf * 1280 + kh * 32));
                LDSM4(al[mf], sb + MATB + aoff + (uint32_t)(mf * 1280 + kh * 32));
            }
            #pragma unroll
            for (int p = 0; p < 2; p++) {
                uint32_t t[4];
                LDSM4(t, sb + 2 * MATB + boff + (uint32_t)(p * 1280 + kh * 32));
                bh[2 * p][0] = t[0]; bh[2 * p][1] = t[1];
                bh[2 * p + 1][0] = t[2]; bh[2 * p + 1][1] = t[3];
                LDSM4(t, sb + 3 * MATB + boff + (uint32_t)(p * 1280 + kh * 32));
                bl[2 * p][0] = t[0]; bl[2 * p][1] = t[1];
                bl[2 * p + 1][0] = t[2]; bl[2 * p + 1][1] = t[3];
            }
            #pragma unroll
            for (int mf = 0; mf < 4; mf++)
                #pragma unroll
                for (int nf = 0; nf < 4; nf++) {
                    MMA_BF16(acc[mf][nf], ah[mf], bh[nf]);
                    MMA_BF16(acc[mf][nf], ah[mf], bl[nf]);
                    MMA_BF16(acc[mf][nf], al[mf], bh[nf]);
                }
        }
    }

    // ---- epilogue: regs -> per-warp smem stage -> coalesced stores ----
    __syncthreads();
    float* stg = (float*)dsm + wid * (16 * 33);
    const int gcol = col0 + wn * 32 + lane;
    const float bv = bias[gcol];
    const int r1 = lane >> 2, c0 = (lane & 3) * 2;

    #pragma unroll
    for (int mf = 0; mf < 4; mf++) {
        #pragma unroll
        for (int nf = 0; nf < 4; nf++) {
            stg[r1 * 33 + nf * 8 + c0]           = acc[mf][nf][0];
            stg[r1 * 33 + nf * 8 + c0 + 1]       = acc[mf][nf][1];
            stg[(r1 + 8) * 33 + nf * 8 + c0]     = acc[mf][nf][2];
            stg[(r1 + 8) * 33 + nf * 8 + c0 + 1] = acc[mf][nf][3];
        }
        __syncwarp();
        const int grow = row0 + wm * 64 + mf * 16;
        #pragma unroll
        for (int r = 0; r < 16; r++) {
            float v = stg[r * 33 + lane] + bv;
            if (EPI == 1) {
                v = gelu_exact(v);
                __nv_bfloat16 h = __float2bfloat16(v);
                Ch[(size_t)(grow + r) * N + gcol] = h;
                Cl[(size_t)(grow + r) * N + gcol] = __float2bfloat16(v - __bfloat162float(h));
            } else {
                Cf[(size_t)(grow + r) * N + gcol] = v;
            }
        }
        __syncwarp();
    }
}

// ============================================================
// weight transpose + bf16 hi/lo split: W[K][N] -> T{h,l}[N][K]
// ============================================================
__global__ void wconv_kernel(const float* __restrict__ W, __nv_bfloat16* __restrict__ Th,
                             __nv_bfloat16* __restrict__ Tl, int K, int N) {
    __shared__ float t[32][33];
    int k0 = blockIdx.x * 32, n0 = blockIdx.y * 32;
    int tx = threadIdx.x, ty = threadIdx.y;  // (32, 8)
    #pragma unroll
    for (int i = 0; i < 4; i++)
        t[ty + i * 8][tx] = W[(size_t)(k0 + ty + i * 8) * N + n0 + tx];
    __syncthreads();
    #pragma unroll
    for (int i = 0; i < 4; i++) {
        int n = n0 + ty + i * 8, k = k0 + tx;
        float v = t[tx][ty + i * 8];
        __nv_bfloat16 h, l;
        split_bf16(v, h, l);
        Th[(size_t)n * K + k] = h;
        Tl[(size_t)n * K + k] = l;
    }
}

// ---------------- elementwise: x = template + positional encoding ----------------
__global__ void add_pe_kernel(const float* __restrict__ t, float* __restrict__ x) {
    int idx = blockIdx.x * 256 + threadIdx.x;
    if (idx >= M_ * D_) return;
    int d = idx % D_;
    int s = (idx / D_) % S_;
    int i2 = d & ~1;
    float div = expf((float)i2 * (-9.210340371976184f / (float)D_));
    float ang = (float)s * div;
    float pe = (d & 1) ? cosf(ang) : sinf(ang);
    x[idx] = t[idx] + pe;
}

// ---------------- pooled = mean over P, emitted as bf16 hi/lo ----------------
__global__ void pool_kernel(const float* __restrict__ ps,
                            __nv_bfloat16* __restrict__ ph, __nv_bfloat16* __restrict__ pl) {
    int idx = blockIdx.x * 256 + threadIdx.x;
    if (idx >= M_ * D_) return;
    int bs = idx / D_;
    int c  = idx % D_;
    const float* base = ps + (size_t)bs * (P_ * D_) + c;
    float s = 0.f;
    #pragma unroll
    for (int p = 0; p < P_; p++) s += base[p * D_];
    float m = s * (1.0f / P_);
    __nv_bfloat16 h, l;
    split_bf16(m, h, l);
    ph[idx] = h; pl[idx] = l;
}

// ---------------- block-reduce helper ----------------
__device__ __forceinline__ float warp_sum(float v) {
    #pragma unroll
    for (int o = 16; o; o >>= 1) v += __shfl_down_sync(0xffffffffu, v, o);
    return v;
}

// ---------------- LayerNorm (row length 768), optional bf16 hi/lo out ----------------
template <int BF16OUT>
__global__ void ln_kernel(const float* __restrict__ x, const float* __restrict__ res,
                          const float* __restrict__ g, const float* __restrict__ b,
                          float* __restrict__ out,
                          __nv_bfloat16* __restrict__ oh, __nv_bfloat16* __restrict__ ol) {
    const int row = blockIdx.x;
    const int tid = threadIdx.x;  // 256
    const float* xr = x + (size_t)row * D_;
    const float* rr = res ? res + (size_t)row * D_ : nullptr;

    float v[3];
    float s = 0.f, s2 = 0.f;
    #pragma unroll
    for (int i = 0; i < 3; i++) {
        float t = xr[tid + i * 256];
        if (rr) t += rr[tid + i * 256];
        v[i] = t; s += t; s2 += t * t;
    }

    __shared__ float red[2][8];
    __shared__ float stat[2];
    int lane = tid & 31, wid = tid >> 5;
    s = warp_sum(s); s2 = warp_sum(s2);
    if (lane == 0) { red[0][wid] = s; red[1][wid] = s2; }
    __syncthreads();
    if (wid == 0) {
        float a = (lane < 8) ? red[0][lane] : 0.f;
        float c = (lane < 8) ? red[1][lane] : 0.f;
        a = warp_sum(a); c = warp_sum(c);
        if (lane == 0) {
            float mean = a * (1.0f / D_);
            float var = c * (1.0f / D_) - mean * mean;
            stat[0] = mean;
            stat[1] = rsqrtf(var + EPS_);
        }
    }
    __syncthreads();
    float mean = stat[0], inv = stat[1];
    float* orow = out + (size_t)row * D_;
    #pragma unroll
    for (int i = 0; i < 3; i++) {
        int c = tid + i * 256;
        float o = (v[i] - mean) * inv * g[c] + b[c];
        orow[c] = o;
        if (BF16OUT) {
            __nv_bfloat16 h, l;
            split_bf16(o, h, l);
            oh[(size_t)row * D_ + c] = h;
            ol[(size_t)row * D_ + c] = l;
        }
    }
}

// ---------------- param_bias[b,h] = (pe_bh @ pe_bh^T) * inv_sqrt_hd ----------------
__global__ __launch_bounds__(256)
void pbias_kernel(const float* __restrict__ enc, float* __restrict__ pbias) {
    __shared__ float Es[112 * 97];
    const int b = blockIdx.x >> 3;
    const int h = blockIdx.x & 7;
    const int tid = threadIdx.x;
    const float* src = enc + (size_t)(b * S_) * D_ + h * HD_;

    for (int i = tid; i < 112 * 96; i += 256) {
        int s = i / 96, d = i - s * 96;
        Es[s * 97 + d] = (s < S_) ? src[(size_t)s * D_ + d] : 0.f;
    }
    __syncthreads();

    const int tx = tid & 15, ty = tid >> 4;
    float acc[7][7];
    #pragma unroll
    for (int ii = 0; ii < 7; ii++)
        #pragma unroll
        for (int jj = 0; jj < 7; jj++) acc[ii][jj] = 0.f;

    for (int d = 0; d < 96; d++) {
        float a[7], bb[7];
        #pragma unroll
        for (int ii = 0; ii < 7; ii++) a[ii]  = Es[(ty + 16 * ii) * 97 + d];
        #pragma unroll
        for (int jj = 0; jj < 7; jj++) bb[jj] = Es[(tx + 16 * jj) * 97 + d];
        #pragma unroll
        for (int ii = 0; ii < 7; ii++)
            #pragma unroll
            for (int jj = 0; jj < 7; jj++) acc[ii][jj] += a[ii] * bb[jj];
    }

    float* dst = pbias + (size_t)blockIdx.x * (S_ * S_);
    #pragma unroll
    for (int ii = 0; ii < 7; ii++) {
        int i = ty + 16 * ii;
        if (i >= S_) continue;
        #pragma unroll
        for (int jj = 0; jj < 7; jj++) {
            int j = tx + 16 * jj;
            if (j < S_) dst[i * S_ + j] = acc[ii][jj] * INV_SQRT_HD;
        }
    }
}

// ---------------- fused attention per (b,h) ----------------
#define ATTN_SMEM ((112 * 97 + 112 * 101) * 4)
__global__ __launch_bounds__(256)
void attn_kernel(const float* __restrict__ x, const float* __restrict__ pbias,
                 float* __restrict__ out) {
    extern __shared__ float smem[];
    float* Qs = smem;               // [112][97]
    float* Ss = smem + 112 * 97;    // [112][101]

    const int b = blockIdx.x >> 3;
    const int h = blockIdx.x & 7;
    const int tid = threadIdx.x;
    const float* xb = x + (size_t)(b * S_) * D_ + h * HD_;

    for (int i = tid; i < 112 * 96; i += 256) {
        int s = i / 96, d = i - s * 96;
        Qs[s * 97 + d] = (s < S_) ? xb[(size_t)s * D_ + d] : 0.f;
    }
    __syncthreads();

    const int tx = tid & 15, ty = tid >> 4;
    {
        float acc[7][7];
        #pragma unroll
        for (int ii = 0; ii < 7; ii++)
            #pragma unroll
            for (int jj = 0; jj < 7; jj++) acc[ii][jj] = 0.f;

        for (int d = 0; d < 96; d++) {
            float a[7], bb[7];
            #pragma unroll
            for (int ii = 0; ii < 7; ii++) a[ii]  = Qs[(ty + 16 * ii) * 97 + d];
            #pragma unroll
            for (int jj = 0; jj < 7; jj++) bb[jj] = Qs[(tx + 16 * jj) * 97 + d];
            #pragma unroll
            for (int ii = 0; ii < 7; ii++)
                #pragma unroll
                for (int jj = 0; jj < 7; jj++) acc[ii][jj] += a[ii] * bb[jj];
        }
        const float* pb = pbias + (size_t)blockIdx.x * (S_ * S_);
        #pragma unroll
        for (int ii = 0; ii < 7; ii++) {
            int i = ty + 16 * ii;
            if (i >= S_) continue;
            #pragma unroll
            for (int jj = 0; jj < 7; jj++) {
                int j = tx + 16 * jj;
                if (j < S_)
                    Ss[i * 101 + j] = acc[ii][jj] * INV_SQRT_HD + pb[i * S_ + j];
            }
        }
    }
    __syncthreads();

    if (tid < S_) {
        float* row = Ss + tid * 101;
        float m = -1e30f;
        for (int j = 0; j < S_; j++) m = fmaxf(m, row[j]);
        float sum = 0.f;
        for (int j = 0; j < S_; j++) { float e = expf(row[j] - m); row[j] = e; sum += e; }
        float inv = 1.0f / sum;
        for (int j = 0; j < S_; j++) row[j] *= inv;
    }
    __syncthreads();

    {
        float acc[7][6];
        #pragma unroll
        for (int ii = 0; ii < 7; ii++)
            #pragma unroll
            for (int jj = 0; jj < 6; jj++) acc[ii][jj] = 0.f;

        for (int j = 0; j < S_; j++) {
            float a[7], bb[6];
            #pragma unroll
            for (int ii = 0; ii < 7; ii++) a[ii]  = Ss[(ty + 16 * ii) * 101 + j];
            #pragma unroll
            for (int jj = 0; jj < 6; jj++) bb[jj] = Qs[j * 97 + tx + 16 * jj];
            #pragma unroll
            for (int ii = 0; ii < 7; ii++)
                #pragma unroll
                for (int jj = 0; jj < 6; jj++) acc[ii][jj] += a[ii] * bb[jj];
        }
        float* dst = out + (size_t)(b * S_) * D_ + h * HD_;
        #pragma unroll
        for (int ii = 0; ii < 7; ii++) {
            int i = ty + 16 * ii;
            if (i >= S_) continue;
            #pragma unroll
            for (int jj = 0; jj < 6; jj++) {
                int dd = tx + 16 * jj;
                dst[(size_t)i * D_ + dd] = acc[ii][jj];
            }
        }
    }
}

// ---------------- final classifier ----------------
__global__ void fc_kernel(const float* __restrict__ x, const float* __restrict__ Wfc,
                          const float* __restrict__ bfc, float* __restrict__ out) {
    const int b = blockIdx.x;
    const int tid = threadIdx.x;
    const float* xr = x + (size_t)b * (S_ * D_);
    float a0 = 0.f, a1 = 0.f;
    for (int i = tid; i < S_ * D_; i += 256) {
        float v = xr[i];
        a0 += v * Wfc[2 * i];
        a1 += v * Wfc[2 * i + 1];
    }
    __shared__ float red[2][8];
    int lane = tid & 31, wid = tid >> 5;
    a0 = warp_sum(a0); a1 = warp_sum(a1);
    if (lane == 0) { red[0][wid] = a0; red[1][wid] = a1; }
    __syncthreads();
    if (wid == 0) {
        float r0 = (lane < 8) ? red[0][lane] : 0.f;
        float r1 = (lane < 8) ? red[1][lane] : 0.f;
        r0 = warp_sum(r0); r1 = warp_sum(r1);
        if (lane == 0) {
            out[2 * b + 0] = r0 + bfc[0];
            out[2 * b + 1] = r1 + bfc[1];
        }
    }
}

// ---------------- launch ----------------
extern "C" void kernel_launch(void* const* d_in, const int* in_sizes, int n_in,
                              void* d_out, int out_size) {
    const float* tseq = (const float*)d_in[0];
    const float* pseq = (const float*)d_in[1];
    const float* Wc  = (const float*)d_in[2];
    const float* bc  = (const float*)d_in[3];
    const float* gp  = (const float*)d_in[4];
    const float* bp  = (const float*)d_in[5];
    const float* W1  = (const float*)d_in[6];
    const float* b1  = (const float*)d_in[7];
    const float* W2  = (const float*)d_in[8];
    const float* b2  = (const float*)d_in[9];
    const float* g1  = (const float*)d_in[10];
    const float* bn1 = (const float*)d_in[11];
    const float* g2  = (const float*)d_in[12];
    const float* bn2 = (const float*)d_in[13];
    const float* Wfc = (const float*)d_in[14];
    const float* bfc = (const float*)d_in[15];
    float* out = (float*)d_out;

    float *x, *enc, *pbias, *tmp;
    __nv_bfloat16 *xhi, *xlo, *phi, *plo, *ffhi, *fflo;
    __nv_bfloat16 *w1h, *w1l, *w2h, *w2l, *wch, *wcl;
    cudaGetSymbolAddress((void**)&x, g_x);
    cudaGetSymbolAddress((void**)&enc, g_enc);
    cudaGetSymbolAddress((void**)&pbias, g_pbias);
    cudaGetSymbolAddress((void**)&tmp, g_tmp);
    cudaGetSymbolAddress((void**)&xhi, g_xhi);
    cudaGetSymbolAddress((void**)&xlo, g_xlo);
    cudaGetSymbolAddress((void**)&phi, g_phi);
    cudaGetSymbolAddress((void**)&plo, g_plo);
    cudaGetSymbolAddress((void**)&ffhi, g_ffhi);
    cudaGetSymbolAddress((void**)&fflo, g_fflo);
    cudaGetSymbolAddress((void**)&w1h, g_w1h);
    cudaGetSymbolAddress((void**)&w1l, g_w1l);
    cudaGetSymbolAddress((void**)&w2h, g_w2h);
    cudaGetSymbolAddress((void**)&w2l, g_w2l);
    cudaGetSymbolAddress((void**)&wch, g_wch);
    cudaGetSymbolAddress((void**)&wcl, g_wcl);

    cudaFuncSetAttribute(attn_kernel, cudaFuncAttributeMaxDynamicSharedMemorySize, ATTN_SMEM);
    cudaFuncSetAttribute(mma_gemm<0>, cudaFuncAttributeMaxDynamicSharedMemorySize, GEMM_SMEM);
    cudaFuncSetAttribute(mma_gemm<1>, cudaFuncAttributeMaxDynamicSharedMemorySize, GEMM_SMEM);

    // weight transpose + split (tiny, one-time per launch)
    wconv_kernel<<<dim3(D_ / 32, FF_ / 32), dim3(32, 8)>>>(W1, w1h, w1l, D_, FF_);
    wconv_kernel<<<dim3(FF_ / 32, D_ / 32), dim3(32, 8)>>>(W2, w2h, w2l, FF_, D_);
    wconv_kernel<<<dim3(D_ / 32, D_ / 32),  dim3(32, 8)>>>(Wc, wch, wcl, D_, D_);

    const int total = M_ * D_;
    add_pe_kernel<<<(total + 255) / 256, 256>>>(tseq, x);
    pool_kernel<<<(total + 255) / 256, 256>>>(pseq, phi, plo);

    // param encoder: enc = LN(pooled @ Wc + bc)
    mma_gemm<0><<<dim3(D_ / BNT, M_ / BMT), 256, GEMM_SMEM>>>(
        phi, plo, wch, wcl, bc, enc, nullptr, nullptr, M_, D_, D_);
    ln_kernel<0><<<M_, 256>>>(enc, nullptr, gp, bp, enc, nullptr, nullptr);

    // layer-invariant attention bias
    pbias_kernel<<<B_ * H_, 256>>>(enc, pbias);

    for (int l = 0; l < NLAYERS; l++) {
        attn_kernel<<<B_ * H_, 256, ATTN_SMEM>>>(x, pbias, tmp);
        ln_kernel<1><<<M_, 256>>>(x, tmp, g1, bn1, x, xhi, xlo);
        mma_gemm<1><<<dim3(FF_ / BNT, M_ / BMT), 256, GEMM_SMEM>>>(
            xhi, xlo, w1h, w1l, b1, nullptr, ffhi, fflo, M_, FF_, D_);
        mma_gemm<0><<<dim3(D_ / BNT, M_ / BMT), 256, GEMM_SMEM>>>(
            ffhi, fflo, w2h, w2l, b2, tmp, nullptr, nullptr, M_, D_, FF_);
        ln_kernel<0><<<M_, 256>>>(x, tmp, g2, bn2, x, nullptr, nullptr);
    }

    fc_kernel<<<B_, 256>>>(x, Wfc, bfc, out);
}